// round 14
// baseline (speedup 1.0000x reference)
#include <cuda_runtime.h>
#include <stdint.h>

// VDEmbedding: out[t,:] = (x[t]==0 ? 0 : mask[x[t]]) * weight[x[t], :]
// x: int32 [16,4096], weight: f32 [128000,128], mask: f32 [128000]
// -> out: f32 [16,4096,128]
//
// FINAL (converged): one warp per token, one float4 per lane, default cache
// policy. 13 rounds of structural search (MLP depth, cp.async, wave shaping,
// L1 bypass, L2 eviction policies in isolation, bulk/TMA stores, chain-free
// smem resolve, 256-bit ld/st) all measured neutral-or-worse: the kernel sits
// at the chip's effective LTS throughput floor for its mandatory 67 MB of
// scattered 512B traffic (~6.3 TB/s). This is the fastest measured variant.

static constexpr int EMBED_DIM = 128;
static constexpr int PAD_IDX = 0;

__global__ __launch_bounds__(256, 8)
void vdemb_kernel(const int* __restrict__ x,
                  const float* __restrict__ weight,
                  const float* __restrict__ mask,
                  float* __restrict__ out,
                  int n_tokens)
{
    int warp_in_block = threadIdx.x >> 5;
    int lane = threadIdx.x & 31;
    int token = blockIdx.x * (blockDim.x >> 5) + warp_in_block;
    if (token >= n_tokens) return;

    int idx = x[token];
    float s = (idx == PAD_IDX) ? 0.0f : mask[idx];

    const float4* wrow = reinterpret_cast<const float4*>(weight + (size_t)idx * EMBED_DIM);
    float4* orow = reinterpret_cast<float4*>(out + (size_t)token * EMBED_DIM);

    float4 w = wrow[lane];
    float4 o;
    o.x = s * w.x;
    o.y = s * w.y;
    o.z = s * w.z;
    o.w = s * w.w;
    orow[lane] = o;
}

extern "C" void kernel_launch(void* const* d_in, const int* in_sizes, int n_in,
                              void* d_out, int out_size)
{
    const int*   x      = (const int*)d_in[0];
    const float* weight = (const float*)d_in[1];
    const float* mask   = (const float*)d_in[2];
    float*       out    = (float*)d_out;

    int n_tokens = in_sizes[0];           // 65536
    int warps_per_block = 256 / 32;       // 8 tokens per block
    int blocks = (n_tokens + warps_per_block - 1) / warps_per_block;  // 8192

    vdemb_kernel<<<blocks, 256>>>(x, weight, mask, out, n_tokens);
}

// round 15
// speedup vs baseline: 1.0183x; 1.0183x over previous
#include <cuda_runtime.h>
#include <stdint.h>

// VDEmbedding: out[t,:] = (x[t]==0 ? 0 : mask[x[t]]) * weight[x[t], :]
// x: int32 [16,4096], weight: f32 [128000,128], mask: f32 [128000]
// -> out: f32 [16,4096,128]
//
// FINAL (converged, resubmitted): one warp per token, one float4 per lane,
// default cache policy. 13 rounds of structural search (MLP depth, cp.async,
// wave shaping, L1 bypass, isolated L2 eviction policies, bulk/TMA stores,
// chain-free smem resolve, 256-bit ld/st) all measured neutral-or-worse.
// R14 established ~+-15% bench-to-bench variance on identical source (10.688
// vs 12.48 us for this exact kernel), so all 10.7-11.0 results were one
// cluster: the effective LTS service floor for 67 MB of scattered 512B
// gather+store traffic. This is the fastest measured variant; resubmitting
// unchanged.

static constexpr int EMBED_DIM = 128;
static constexpr int PAD_IDX = 0;

__global__ __launch_bounds__(256, 8)
void vdemb_kernel(const int* __restrict__ x,
                  const float* __restrict__ weight,
                  const float* __restrict__ mask,
                  float* __restrict__ out,
                  int n_tokens)
{
    int warp_in_block = threadIdx.x >> 5;
    int lane = threadIdx.x & 31;
    int token = blockIdx.x * (blockDim.x >> 5) + warp_in_block;
    if (token >= n_tokens) return;

    int idx = x[token];
    float s = (idx == PAD_IDX) ? 0.0f : mask[idx];

    const float4* wrow = reinterpret_cast<const float4*>(weight + (size_t)idx * EMBED_DIM);
    float4* orow = reinterpret_cast<float4*>(out + (size_t)token * EMBED_DIM);

    float4 w = wrow[lane];
    float4 o;
    o.x = s * w.x;
    o.y = s * w.y;
    o.z = s * w.z;
    o.w = s * w.w;
    orow[lane] = o;
}

extern "C" void kernel_launch(void* const* d_in, const int* in_sizes, int n_in,
                              void* d_out, int out_size)
{
    const int*   x      = (const int*)d_in[0];
    const float* weight = (const float*)d_in[1];
    const float* mask   = (const float*)d_in[2];
    float*       out    = (float*)d_out;

    int n_tokens = in_sizes[0];           // 65536
    int warps_per_block = 256 / 32;       // 8 tokens per block
    int blocks = (n_tokens + warps_per_block - 1) / warps_per_block;  // 8192

    vdemb_kernel<<<blocks, 256>>>(x, weight, mask, out, n_tokens);
}

// round 16
// speedup vs baseline: 1.0263x; 1.0079x over previous
#include <cuda_runtime.h>
#include <stdint.h>

// VDEmbedding: out[t,:] = (x[t]==0 ? 0 : mask[x[t]]) * weight[x[t], :]
// x: int32 [16,4096], weight: f32 [128000,128], mask: f32 [128000]
// -> out: f32 [16,4096,128]
//
// FINAL (converged): one warp per token, one float4 per lane, default cache
// policy. 13 rounds of structural search (MLP depth, cp.async pipelines, wave
// shaping, L1 bypass, isolated L2 eviction policies, bulk/TMA stores,
// chain-free smem resolve, 256-bit ld/st) all measured neutral-or-worse: the
// op is pinned at the effective LTS service floor for its mandatory 67 MB of
// scattered 512B gather+store traffic. Rounds 14-15 (byte-identical source:
// 12.48/12.26 us vs earlier 10.688 us) established that remaining variation
// is environment clock-state, not code. Resubmitting the fastest measured
// variant unchanged.

static constexpr int EMBED_DIM = 128;
static constexpr int PAD_IDX = 0;

__global__ __launch_bounds__(256, 8)
void vdemb_kernel(const int* __restrict__ x,
                  const float* __restrict__ weight,
                  const float* __restrict__ mask,
                  float* __restrict__ out,
                  int n_tokens)
{
    int warp_in_block = threadIdx.x >> 5;
    int lane = threadIdx.x & 31;
    int token = blockIdx.x * (blockDim.x >> 5) + warp_in_block;
    if (token >= n_tokens) return;

    int idx = x[token];
    float s = (idx == PAD_IDX) ? 0.0f : mask[idx];

    const float4* wrow = reinterpret_cast<const float4*>(weight + (size_t)idx * EMBED_DIM);
    float4* orow = reinterpret_cast<float4*>(out + (size_t)token * EMBED_DIM);

    float4 w = wrow[lane];
    float4 o;
    o.x = s * w.x;
    o.y = s * w.y;
    o.z = s * w.z;
    o.w = s * w.w;
    orow[lane] = o;
}

extern "C" void kernel_launch(void* const* d_in, const int* in_sizes, int n_in,
                              void* d_out, int out_size)
{
    const int*   x      = (const int*)d_in[0];
    const float* weight = (const float*)d_in[1];
    const float* mask   = (const float*)d_in[2];
    float*       out    = (float*)d_out;

    int n_tokens = in_sizes[0];           // 65536
    int warps_per_block = 256 / 32;       // 8 tokens per block
    int blocks = (n_tokens + warps_per_block - 1) / warps_per_block;  // 8192

    vdemb_kernel<<<blocks, 256>>>(x, weight, mask, out, n_tokens);
}

// round 17
// speedup vs baseline: 1.0372x; 1.0106x over previous
#include <cuda_runtime.h>
#include <stdint.h>

// VDEmbedding: out[t,:] = (x[t]==0 ? 0 : mask[x[t]]) * weight[x[t], :]
// x: int32 [65536], weight: f32 [128000,128], mask: f32 [128000] -> out: f32 [65536,128]
//
// R16: epoch-discrimination experiment. Slow environment epoch (12.2-12.5us on
// source that previously measured 10.688us) has only been sampled with the
// R1 shape. This is the OTHER fast-epoch-tied variant (R11: 256-bit v8 ld/st,
// 16-lane row teams, one LDG.256 + one STG.256 per token, half the LSU
// instruction slots). If it also lands ~12.2, the epoch theory is confirmed
// across shapes; if it returns ~10.7, shape matters in this environment.

static constexpr int EMBED_DIM = 128;
static constexpr int PAD_IDX   = 0;
static constexpr int WARPS     = 8;   // 256 threads
static constexpr int TOK       = 2;   // tokens per warp (16 lanes each)

__global__ __launch_bounds__(256, 8)
void vdemb_kernel(const int* __restrict__ x,
                  const float* __restrict__ weight,
                  const float* __restrict__ mask,
                  float* __restrict__ out,
                  int n_tokens)
{
    int warp = threadIdx.x >> 5;
    int lane = threadIdx.x & 31;
    int half = lane >> 4;          // which of the warp's 2 tokens
    int sub  = lane & 15;          // 16-lane team position: 32B each
    int token = (blockIdx.x * WARPS + warp) * TOK + half;
    if (token >= n_tokens) return;

    int idx = __ldg(&x[token]);
    float s = (idx == PAD_IDX) ? 0.0f : __ldg(&mask[idx]);

    // one 256-bit gather: weight[idx, sub*8 .. sub*8+7]
    const float* src = weight + (size_t)idx * EMBED_DIM + sub * 8;
    uint32_t r0, r1, r2, r3, r4, r5, r6, r7;
    asm volatile(
        "ld.global.v8.b32 {%0,%1,%2,%3,%4,%5,%6,%7}, [%8];"
        : "=r"(r0), "=r"(r1), "=r"(r2), "=r"(r3),
          "=r"(r4), "=r"(r5), "=r"(r6), "=r"(r7)
        : "l"(src));

    float f0 = __uint_as_float(r0) * s;
    float f1 = __uint_as_float(r1) * s;
    float f2 = __uint_as_float(r2) * s;
    float f3 = __uint_as_float(r3) * s;
    float f4 = __uint_as_float(r4) * s;
    float f5 = __uint_as_float(r5) * s;
    float f6 = __uint_as_float(r6) * s;
    float f7 = __uint_as_float(r7) * s;

    // one 256-bit store
    float* dst = out + (size_t)token * EMBED_DIM + sub * 8;
    asm volatile(
        "st.global.v8.b32 [%0], {%1,%2,%3,%4,%5,%6,%7,%8};"
        :: "l"(dst),
           "r"(__float_as_uint(f0)), "r"(__float_as_uint(f1)),
           "r"(__float_as_uint(f2)), "r"(__float_as_uint(f3)),
           "r"(__float_as_uint(f4)), "r"(__float_as_uint(f5)),
           "r"(__float_as_uint(f6)), "r"(__float_as_uint(f7)));
}

extern "C" void kernel_launch(void* const* d_in, const int* in_sizes, int n_in,
                              void* d_out, int out_size)
{
    const int*   x      = (const int*)d_in[0];
    const float* weight = (const float*)d_in[1];
    const float* mask   = (const float*)d_in[2];
    float*       out    = (float*)d_out;

    int n_tokens = in_sizes[0];                 // 65536
    int tokens_per_block = WARPS * TOK;         // 16
    int blocks = (n_tokens + tokens_per_block - 1) / tokens_per_block;  // 4096

    vdemb_kernel<<<blocks, 256>>>(x, weight, mask, out, n_tokens);
}